// round 5
// baseline (speedup 1.0000x reference)
#include <cuda_runtime.h>
#include <cuda_bf16.h>

#define T_LEN 16384
#define NTAG  1024
#define NCTA  128
#define NCOL  8          // NTAG / NCTA columns per CTA
#define NTHR  256

// ---------------- persistent device state (recomputed every launch) ----------------
__device__ float          d_S[2][NTAG];          // double-buffered linear state
__device__ float          d_maxslot[T_LEN];      // per-step max(S_t) via red.max (int-compare)
__device__ int            d_bar[T_LEN];          // per-step arrival counters
__device__ __nv_bfloat16  d_E[NTAG * NTAG];      // E[k][j] = exp(trans[j][k]), k-major
__device__ double         d_score;               // gold-path score

// ---------------- memory-model helpers ----------------
__device__ __forceinline__ int ld_acquire_gpu(const int* p) {
    int v;
    asm volatile("ld.acquire.gpu.global.s32 %0, [%1];" : "=r"(v) : "l"(p) : "memory");
    return v;
}
__device__ __forceinline__ void red_release_add(int* p, int v) {
    asm volatile("red.release.gpu.global.add.s32 [%0], %1;" :: "l"(p), "r"(v) : "memory");
}
__device__ __forceinline__ void red_max_posf(float* p, float v) {
    // positive floats order identically to their int bit patterns
    asm volatile("red.relaxed.gpu.global.max.s32 [%0], %1;" :: "l"(p), "r"(__float_as_int(v)) : "memory");
}

// ---------------- setup kernels ----------------
__global__ void zero_state_kernel() {
    int i = blockIdx.x * blockDim.x + threadIdx.x;
    if (i < T_LEN) { d_bar[i] = 0; d_maxslot[i] = 0.0f; }
}

__global__ void build_E_kernel(const float* __restrict__ trans) {
    int i = blockIdx.x * blockDim.x + threadIdx.x;  // i = k*1024 + j
    int k = i >> 10;
    int j = i & (NTAG - 1);
    d_E[i] = __float2bfloat16(__expf(trans[j * NTAG + k]));
}

__global__ void __launch_bounds__(256) gold_score_kernel(
    const float* __restrict__ emit, const int* __restrict__ y,
    const float* __restrict__ trans, const float* __restrict__ strans,
    const float* __restrict__ etrans)
{
    __shared__ double sd[256];
    int tid = threadIdx.x;
    double a = 0.0;
    for (int t = tid; t < T_LEN; t += 256)
        a += (double)emit[(size_t)t * NTAG + y[t]];
    for (int t = tid; t < T_LEN - 1; t += 256)
        a += (double)trans[(size_t)y[t] * NTAG + y[t + 1]];
    if (tid == 0)
        a += (double)strans[y[0]] + (double)etrans[y[T_LEN - 1]];
    sd[tid] = a;
    __syncthreads();
    for (int s = 128; s; s >>= 1) {
        if (tid < s) sd[tid] += sd[tid + s];
        __syncthreads();
    }
    if (tid == 0) d_score = sd[0];
}

// ---------------- main persistent scan kernel ----------------
__global__ void __launch_bounds__(NTHR, 1) crf_scan_kernel(
    const float* __restrict__ emit,
    const float* __restrict__ strans,
    const float* __restrict__ etrans,
    float* __restrict__ out)
{
    __shared__ __nv_bfloat16 sE[NCOL][NTAG];   // 16 KB: this CTA's 8 E columns
    __shared__ float  sred[8][NCOL];           // cross-warp partials
    __shared__ double sdbl[NTHR];

    const int tid  = threadIdx.x;
    const int w    = tid >> 5;
    const int lane = tid & 31;
    const int cta  = blockIdx.x;
    const int k0   = cta * NCOL;
    const int j0   = w * 128 + lane * 4;       // this thread's 4 j-indices

    // ---- load our E columns into SMEM (16 KB contiguous) ----
    {
        const float4* src = (const float4*)(d_E + (size_t)k0 * NTAG);
        float4* dst = (float4*)(&sE[0][0]);
        #pragma unroll
        for (int i = tid; i < (NCOL * NTAG * 2) / 16; i += NTHR) dst[i] = src[i];
    }
    __syncthreads();

    // ---- step 0: S_0[k] = exp(strans[k] + emit[0,k]) ----
    if (tid < NCOL) {
        float v = __expf(strans[k0 + tid] + emit[k0 + tid]);
        d_S[0][k0 + tid] = v;
        red_max_posf(&d_maxslot[0], v);
    }
    float e_nxt = 0.0f;
    if (tid < NCOL) e_nxt = __ldg(&emit[(size_t)1 * NTAG + k0 + tid]);  // prefetch row 1
    __syncwarp();
    if (tid == 0) red_release_add(&d_bar[0], 1);

    // ---- sequential scan ----
    for (int t = 1; t < T_LEN; ++t) {
        float g = 0.0f;
        if (tid < NCOL) g = __expf(e_nxt);     // exp(emit[t,k]) computed in barrier shadow

        if (w == 0) { while (ld_acquire_gpu(&d_bar[t - 1]) < NCTA) {} }
        __syncthreads();

        const float* Sprev = d_S[(t - 1) & 1];
        float inv_m = 0.0f;
        if (tid < NCOL) inv_m = __fdividef(1.0f, __ldcg(&d_maxslot[t - 1]));

        float4 s4 = __ldcg((const float4*)(Sprev + j0));   // fresh from L2 (bypass L1)

        if (tid < NCOL && t + 1 < T_LEN)
            e_nxt = __ldg(&emit[(size_t)(t + 1) * NTAG + k0 + tid]);  // prefetch next row

        float acc[NCOL];
        #pragma unroll
        for (int c = 0; c < NCOL; ++c) {
            const __nv_bfloat162* e2 = (const __nv_bfloat162*)(&sE[c][j0]);
            float2 a = __bfloat1622float2(e2[0]);
            float2 b = __bfloat1622float2(e2[1]);
            acc[c] = s4.x * a.x + s4.y * a.y + s4.z * b.x + s4.w * b.y;
        }
        #pragma unroll
        for (int off = 16; off; off >>= 1) {
            #pragma unroll
            for (int c = 0; c < NCOL; ++c)
                acc[c] += __shfl_xor_sync(0xffffffffu, acc[c], off);
        }
        if (lane < NCOL) sred[w][lane] = acc[lane];
        __syncthreads();

        if (tid < NCOL) {
            float p = sred[0][tid] + sred[1][tid] + sred[2][tid] + sred[3][tid]
                    + sred[4][tid] + sred[5][tid] + sred[6][tid] + sred[7][tid];
            float v = p * inv_m * g;
            d_S[t & 1][k0 + tid] = v;
            red_max_posf(&d_maxslot[t], v);
        }
        __syncwarp();
        if (tid == 0) red_release_add(&d_bar[t], 1);
    }

    // ---- finalize (CTA 0 only) ----
    if (cta != 0) return;
    if (w == 0) { while (ld_acquire_gpu(&d_bar[T_LEN - 1]) < NCTA) {} }
    __syncthreads();

    const float* Sfin = d_S[(T_LEN - 1) & 1];
    double a1 = 0.0;
    for (int k = tid; k < NTAG; k += NTHR)
        a1 += (double)__ldcg(&Sfin[k]) * (double)__expf(etrans[k]);
    sdbl[tid] = a1;
    __syncthreads();
    for (int s = NTHR / 2; s; s >>= 1) {
        if (tid < s) sdbl[tid] += sdbl[tid + s];
        __syncthreads();
    }
    double sumS = sdbl[0];
    __syncthreads();

    double a2 = 0.0;
    for (int t = tid; t < T_LEN - 1; t += NTHR)
        a2 += (double)logf(__ldcg(&d_maxslot[t]));
    sdbl[tid] = a2;
    __syncthreads();
    for (int s = NTHR / 2; s; s >>= 1) {
        if (tid < s) sdbl[tid] += sdbl[tid + s];
        __syncthreads();
    }
    if (tid == 0) {
        double logZ = sdbl[0] + log(sumS);
        out[0] = (float)(logZ - d_score);
    }
}

// ---------------- entry point ----------------
extern "C" void kernel_launch(void* const* d_in, const int* in_sizes, int n_in,
                              void* d_out, int out_size)
{
    const float* emit   = (const float*)d_in[0];
    const int*   y      = (const int*)  d_in[1];
    const float* trans  = (const float*)d_in[2];
    const float* strans = (const float*)d_in[3];
    const float* etrans = (const float*)d_in[4];
    float* out = (float*)d_out;

    zero_state_kernel<<<(T_LEN + 255) / 256, 256>>>();
    build_E_kernel<<<(NTAG * NTAG) / 256, 256>>>(trans);
    gold_score_kernel<<<1, 256>>>(emit, y, trans, strans, etrans);
    crf_scan_kernel<<<NCTA, NTHR>>>(emit, strans, etrans, out);
}

// round 16
// speedup vs baseline: 1.0155x; 1.0155x over previous
#include <cuda_runtime.h>

#define T_LEN 16384
#define NTAG  1024
#define NCTA  128
#define NCOL  8          // NTAG / NCTA columns per CTA
#define NTHR  256

// ---------------- persistent device state (recomputed every launch) ----------------
__device__ float  d_S[2][NTAG];          // double-buffered linear state (R4-proven ring)
__device__ float  d_maxslot[T_LEN];      // per-step max(S_t) via red.max (int-compare on positives)
__device__ int    d_bar[T_LEN];          // per-step arrival counters (R4-proven)
__device__ double d_score;               // gold-path score

// ---------------- memory-model helpers (R4-proven set) ----------------
__device__ __forceinline__ int ld_acquire_gpu(const int* p) {
    int v;
    asm volatile("ld.acquire.gpu.global.s32 %0, [%1];" : "=r"(v) : "l"(p) : "memory");
    return v;
}
__device__ __forceinline__ void red_release_add(int* p, int v) {
    asm volatile("red.release.gpu.global.add.s32 [%0], %1;" :: "l"(p), "r"(v) : "memory");
}
__device__ __forceinline__ void red_max_posf(float* p, float v) {
    // positive floats order identically to their int bit patterns
    asm volatile("red.relaxed.gpu.global.max.s32 [%0], %1;" :: "l"(p), "r"(__float_as_int(v)) : "memory");
}
__device__ __forceinline__ float ld_cg_f32(const float* p) {
    float v;
    asm volatile("ld.global.cg.f32 %0, [%1];" : "=f"(v) : "l"(p) : "memory");
    return v;
}
__device__ __forceinline__ float4 ld_cg_v4(const float* p) {
    float4 v;
    asm volatile("ld.global.cg.v4.f32 {%0,%1,%2,%3}, [%4];"
                 : "=f"(v.x), "=f"(v.y), "=f"(v.z), "=f"(v.w)
                 : "l"(p) : "memory");
    return v;
}
__device__ __forceinline__ void st_cg_f32(float* p, float v) {
    asm volatile("st.global.cg.f32 [%0], %1;" :: "l"(p), "f"(v) : "memory");
}

// ---------------- setup kernels ----------------
__global__ void zero_state_kernel() {
    int i = blockIdx.x * blockDim.x + threadIdx.x;
    if (i < T_LEN) { d_bar[i] = 0; d_maxslot[i] = 0.0f; }
}

__global__ void __launch_bounds__(256) gold_score_kernel(
    const float* __restrict__ emit, const int* __restrict__ y,
    const float* __restrict__ trans, const float* __restrict__ strans,
    const float* __restrict__ etrans)
{
    __shared__ double sd[256];
    int tid = threadIdx.x;
    double a = 0.0;
    for (int t = tid; t < T_LEN; t += 256)
        a += (double)emit[(size_t)t * NTAG + y[t]];
    for (int t = tid; t < T_LEN - 1; t += 256)
        a += (double)trans[(size_t)y[t] * NTAG + y[t + 1]];
    if (tid == 0)
        a += (double)strans[y[0]] + (double)etrans[y[T_LEN - 1]];
    sd[tid] = a;
    __syncthreads();
    for (int s = 128; s; s >>= 1) {
        if (tid < s) sd[tid] += sd[tid + s];
        __syncthreads();
    }
    if (tid == 0) d_score = sd[0];
}

// ---------------- main persistent scan kernel (R4 flow, E in fp32 registers) ----------------
__global__ void __launch_bounds__(NTHR, 1) crf_scan_kernel(
    const float* __restrict__ emit,
    const float* __restrict__ trans,
    const float* __restrict__ strans,
    const float* __restrict__ etrans,
    float* __restrict__ out)
{
    __shared__ float  sred[8][NCOL];     // cross-warp partials
    __shared__ double sdbl[NTHR];

    const int tid  = threadIdx.x;
    const int w    = tid >> 5;
    const int lane = tid & 31;
    const int cta  = blockIdx.x;
    const int k0   = cta * NCOL;
    const int j0   = w * 128 + lane * 4;       // this thread's 4 j-indices

    // ---- this thread's 8x4 slice of E = exp(trans), fp32, in registers ----
    // (replaces R4's bf16 SMEM tile: removes per-step LDS + converts from the
    //  serial chain; pure per-CTA arithmetic change, no effect on synchronization)
    float e[NCOL][4];
    #pragma unroll
    for (int c = 0; c < NCOL; ++c)
        #pragma unroll
        for (int i = 0; i < 4; ++i)
            e[c][i] = __expf(__ldg(&trans[(size_t)(j0 + i) * NTAG + (k0 + c)]));

    // ---- step 0: S_0[k] = exp(strans[k] + emit[0,k]) ----
    if (tid < NCOL) {
        float v = __expf(strans[k0 + tid] + emit[k0 + tid]);
        st_cg_f32(&d_S[0][k0 + tid], v);
        red_max_posf(&d_maxslot[0], v);
    }
    float e_nxt = 0.0f;
    if (tid < NCOL) e_nxt = __ldg(&emit[NTAG + k0 + tid]);   // prefetch row 1
    __syncwarp();
    if (tid == 0) red_release_add(&d_bar[0], 1);

    // ---- sequential scan (R4-proven barrier semantics, unchanged) ----
    for (int t = 1; t < T_LEN; ++t) {
        float g = 0.0f;
        if (tid < NCOL) g = __expf(e_nxt);     // exp(emit[t,k]) in the barrier shadow

        if (w == 0) { while (ld_acquire_gpu(&d_bar[t - 1]) < NCTA) {} }
        __syncthreads();

        float inv_m = 0.0f;
        if (tid < NCOL) inv_m = __fdividef(1.0f, ld_cg_f32(&d_maxslot[t - 1]));

        float4 s4 = ld_cg_v4(&d_S[(t - 1) & 1][j0]);   // fresh from L2

        if (tid < NCOL && t + 1 < T_LEN)
            e_nxt = __ldg(&emit[(size_t)(t + 1) * NTAG + k0 + tid]);  // prefetch next row

        float acc[NCOL];
        #pragma unroll
        for (int c = 0; c < NCOL; ++c)
            acc[c] = (s4.x * e[c][0] + s4.y * e[c][1]) + (s4.z * e[c][2] + s4.w * e[c][3]);

        #pragma unroll
        for (int off = 16; off; off >>= 1) {
            #pragma unroll
            for (int c = 0; c < NCOL; ++c)
                acc[c] += __shfl_xor_sync(0xffffffffu, acc[c], off);
        }
        if (lane < NCOL) sred[w][lane] = acc[lane];
        __syncthreads();

        if (tid < NCOL) {
            float p = ((sred[0][tid] + sred[1][tid]) + (sred[2][tid] + sred[3][tid]))
                    + ((sred[4][tid] + sred[5][tid]) + (sred[6][tid] + sred[7][tid]));
            float v = p * inv_m * g;
            st_cg_f32(&d_S[t & 1][k0 + tid], v);
            red_max_posf(&d_maxslot[t], v);
        }
        __syncwarp();
        if (tid == 0) red_release_add(&d_bar[t], 1);
    }

    // ---- finalize (CTA 0 only) ----
    if (cta != 0) return;
    if (w == 0) { while (ld_acquire_gpu(&d_bar[T_LEN - 1]) < NCTA) {} }
    __syncthreads();

    float4 s = ld_cg_v4(&d_S[(T_LEN - 1) & 1][tid * 4]);
    double a1 = (double)s.x * exp((double)etrans[tid * 4 + 0])
              + (double)s.y * exp((double)etrans[tid * 4 + 1])
              + (double)s.z * exp((double)etrans[tid * 4 + 2])
              + (double)s.w * exp((double)etrans[tid * 4 + 3]);
    sdbl[tid] = a1;
    __syncthreads();
    for (int st = NTHR / 2; st; st >>= 1) {
        if (tid < st) sdbl[tid] += sdbl[tid + st];
        __syncthreads();
    }
    double sumS = sdbl[0];
    __syncthreads();

    double a2 = 0.0;
    for (int t = tid; t < T_LEN - 1; t += NTHR)
        a2 += log((double)ld_cg_f32(&d_maxslot[t]));   // final values, consistent with applied scales
    sdbl[tid] = a2;
    __syncthreads();
    for (int st = NTHR / 2; st; st >>= 1) {
        if (tid < st) sdbl[tid] += sdbl[tid + st];
        __syncthreads();
    }
    if (tid == 0) {
        double logZ = sdbl[0] + log(sumS);
        out[0] = (float)(logZ - d_score);
    }
}

// ---------------- entry point ----------------
extern "C" void kernel_launch(void* const* d_in, const int* in_sizes, int n_in,
                              void* d_out, int out_size)
{
    const float* emit   = (const float*)d_in[0];
    const int*   y      = (const int*)  d_in[1];
    const float* trans  = (const float*)d_in[2];
    const float* strans = (const float*)d_in[3];
    const float* etrans = (const float*)d_in[4];
    float* out = (float*)d_out;

    zero_state_kernel<<<(T_LEN + 255) / 256, 256>>>();
    gold_score_kernel<<<1, 256>>>(emit, y, trans, strans, etrans);
    crf_scan_kernel<<<NCTA, NTHR>>>(emit, trans, strans, etrans, out);
}